// round 5
// baseline (speedup 1.0000x reference)
#include <cuda_runtime.h>
#include <math.h>
#include <stdint.h>

// ---------------------------------------------------------------------------
// HashEncoderHyFluid, R4: Morton sort for gather locality (R3) + line-granular
// scattered output writes. Each query's 32-float output row is one 128B cache
// line; 8 lanes cooperatively write one row so scattered stores cost 1
// wavefront/query (was 32 in R3). Pipeline: zero -> hist -> scan -> scatter ->
// encode(sorted, smem transpose, row-granular scatter-out).
// ---------------------------------------------------------------------------

#define CAP   (1 << 20)     // max queries supported by sort scratch
#define NBINS (1 << 18)     // 18-bit Morton key: x5 y5 z4 t4

__device__ float4   g_sorted[CAP];
__device__ unsigned g_oidx[CAP];
__device__ unsigned g_hist[NBINS];

struct Level {
    float    rf0, rf1, rf2, rf3;
    unsigned s1, s2, s3;           // dense strides
    unsigned mask;                 // size-1 (hashed pow2)
    unsigned size;
    int      offset;               // float offset into hash_table
    int      mode;                 // 0 dense, 1 hash+mask, 2 hash+mod
};
struct KConfig { Level lv[16]; };

#define HPRIME1 2654435761u
#define HPRIME2 805459861u
#define HPRIME3 3674653429u

// ---------------- sort kernels ----------------

__device__ __forceinline__ unsigned morton_key(float4 X)
{
    unsigned kx = (unsigned)(X.x * 32.f); if (kx > 31u) kx = 31u;
    unsigned ky = (unsigned)(X.y * 32.f); if (ky > 31u) ky = 31u;
    unsigned kz = (unsigned)(X.z * 16.f); if (kz > 15u) kz = 15u;
    unsigned kt = (unsigned)(X.w * 16.f); if (kt > 15u) kt = 15u;
    unsigned key = 0;
    #pragma unroll
    for (int b = 4; b >= 0; --b) {
        key = (key << 1) | ((kx >> b) & 1u);
        key = (key << 1) | ((ky >> b) & 1u);
        if (b < 4) {
            key = (key << 1) | ((kz >> b) & 1u);
            key = (key << 1) | ((kt >> b) & 1u);
        }
    }
    return key;   // 18 bits
}

__global__ void zero_hist_kernel()
{
    int i = blockIdx.x * blockDim.x + threadIdx.x;
    if (i < NBINS) g_hist[i] = 0u;
}

__global__ void hist_kernel(const float4* __restrict__ xyzt, int n)
{
    int i = blockIdx.x * blockDim.x + threadIdx.x;
    if (i >= n) return;
    atomicAdd(&g_hist[morton_key(xyzt[i])], 1u);
}

// single block, 1024 threads; each thread owns NBINS/1024 = 256 bins
__global__ __launch_bounds__(1024)
void scan_kernel()
{
    __shared__ unsigned sh[1024];
    const int t = threadIdx.x;
    const int per = NBINS / 1024;
    const unsigned base = (unsigned)t * per;

    unsigned sum = 0;
    for (int i = 0; i < per; ++i) sum += g_hist[base + i];
    sh[t] = sum;
    __syncthreads();
    for (int off = 1; off < 1024; off <<= 1) {
        unsigned v = (t >= off) ? sh[t - off] : 0u;
        __syncthreads();
        sh[t] += v;
        __syncthreads();
    }
    unsigned run = sh[t] - sum;
    for (int i = 0; i < per; ++i) {
        unsigned h = g_hist[base + i];
        g_hist[base + i] = run;
        run += h;
    }
}

__global__ void scatter_kernel(const float4* __restrict__ xyzt, int n)
{
    int i = blockIdx.x * blockDim.x + threadIdx.x;
    if (i >= n) return;
    float4 X = xyzt[i];
    unsigned pos = atomicAdd(&g_hist[morton_key(X)], 1u);
    g_sorted[pos] = X;
    g_oidx[pos]   = (unsigned)i;
}

// ---------------- encode ----------------

__device__ __forceinline__ void acc_pair128(const float2* __restrict__ t2,
                                            unsigned i0, float w0, float w1,
                                            float& a0, float& a1)
{
    unsigned m = i0 & ~1u;
    float4 f = __ldg(reinterpret_cast<const float4*>(t2 + m));
    bool odd = (i0 & 1u);
    float c0x = odd ? f.z : f.x, c0y = odd ? f.w : f.y;
    float c1x = odd ? f.x : f.z, c1y = odd ? f.y : f.w;
    a0 += w0 * c0x + w1 * c1x;
    a1 += w0 * c0y + w1 * c1y;
}

__device__ __forceinline__ void encode_level(const float4& X,
                                             const Level& L,
                                             const float* __restrict__ tab,
                                             float& a0, float& a1)
{
    float px = X.x * L.rf0, py = X.y * L.rf1, pz = X.z * L.rf2, pt = X.w * L.rf3;
    float gx = floorf(px),  gy = floorf(py),  gz = floorf(pz),  gt = floorf(pt);
    float fx = px - gx,     fy = py - gy,     fz = pz - gz,     ft = pt - gt;
    unsigned cx = (unsigned)(int)gx, cy = (unsigned)(int)gy;
    unsigned cz = (unsigned)(int)gz, ct = (unsigned)(int)gt;

    float wx0 = 1.f - fx, wy0 = 1.f - fy, wz0 = 1.f - fz, wt0 = 1.f - ft;
    float wxy[4], wzt[4];
    wxy[0] = wx0 * wy0;  wxy[1] = fx * wy0;  wxy[2] = wx0 * fy;  wxy[3] = fx * fy;
    wzt[0] = wz0 * wt0;  wzt[1] = fz * wt0;  wzt[2] = wz0 * ft;  wzt[3] = fz * ft;

    const float2* t2 = reinterpret_cast<const float2*>(tab) + (L.offset >> 1);
    a0 = 0.f; a1 = 0.f;

    if (L.mode == 0) {
        unsigned bxy = cx + cy * L.s1;
        unsigned ixy0[2] = { bxy, bxy + L.s1 };
        unsigned bzt = cz * L.s2 + ct * L.s3;
        unsigned izt[4] = { bzt, bzt + L.s2, bzt + L.s3, bzt + L.s2 + L.s3 };
        #pragma unroll
        for (int j = 0; j < 4; ++j) {
            #pragma unroll
            for (int b = 0; b < 2; ++b) {
                unsigned i0 = ixy0[b] + izt[j];
                float w0 = wxy[2 * b]     * wzt[j];
                float w1 = wxy[2 * b + 1] * wzt[j];
                if ((i0 & 1u) == 0u) {
                    acc_pair128(t2, i0, w0, w1, a0, a1);
                } else {
                    float2 f0 = __ldg(t2 + i0);
                    float2 f1 = __ldg(t2 + i0 + 1u);
                    a0 += w0 * f0.x + w1 * f1.x;
                    a1 += w0 * f0.y + w1 * f1.y;
                }
            }
        }
    } else {
        unsigned hy = cy * HPRIME1, hz = cz * HPRIME2, ht = ct * HPRIME3;
        unsigned msk = L.mask;
        unsigned rxy0[2] = { hy, hy + HPRIME1 };
        unsigned izt[4] = { hz ^ ht, (hz + HPRIME2) ^ ht,
                            hz ^ (ht + HPRIME3), (hz + HPRIME2) ^ (ht + HPRIME3) };
        if (L.mode == 1) {
            if ((cx & 1u) == 0u) {
                #pragma unroll
                for (int j = 0; j < 4; ++j) {
                    #pragma unroll
                    for (int b = 0; b < 2; ++b) {
                        unsigned i0 = (cx ^ rxy0[b] ^ izt[j]) & msk;
                        acc_pair128(t2, i0,
                                    wxy[2 * b] * wzt[j], wxy[2 * b + 1] * wzt[j],
                                    a0, a1);
                    }
                }
            } else {
                unsigned cx1 = cx + 1u;
                #pragma unroll
                for (int j = 0; j < 4; ++j) {
                    #pragma unroll
                    for (int b = 0; b < 2; ++b) {
                        unsigned r = rxy0[b] ^ izt[j];
                        unsigned i0 = (cx  ^ r) & msk;
                        unsigned i1 = (cx1 ^ r) & msk;
                        float w0 = wxy[2 * b]     * wzt[j];
                        float w1 = wxy[2 * b + 1] * wzt[j];
                        float2 f0 = __ldg(t2 + i0);
                        float2 f1 = __ldg(t2 + i1);
                        a0 += w0 * f0.x + w1 * f1.x;
                        a1 += w0 * f0.y + w1 * f1.y;
                    }
                }
            }
        } else {
            unsigned sz = L.size, cx1 = cx + 1u;
            #pragma unroll
            for (int j = 0; j < 4; ++j) {
                #pragma unroll
                for (int b = 0; b < 2; ++b) {
                    unsigned r = rxy0[b] ^ izt[j];
                    unsigned i0 = (cx  ^ r) % sz;
                    unsigned i1 = (cx1 ^ r) % sz;
                    float w0 = wxy[2 * b]     * wzt[j];
                    float w1 = wxy[2 * b + 1] * wzt[j];
                    float2 f0 = __ldg(t2 + i0);
                    float2 f1 = __ldg(t2 + i1);
                    a0 += w0 * f0.x + w1 * f1.x;
                    a1 += w0 * f0.y + w1 * f1.y;
                }
            }
        }
    }
}

// smem row stride: 36 floats (144 B, 16B-aligned; 36%32=4 banks skew ->
// conflict-free STS.128 across threads and LDS.128 across 8-lane row groups)
#define SH_STRIDE 36

template <bool SORTED>
__global__ __launch_bounds__(256)
void hashenc_kernel(const float4* __restrict__ coords,
                    const float*  __restrict__ tab,
                    float*        __restrict__ out,
                    KConfig cfg, int n)
{
    __shared__ float sh[256 * SH_STRIDE];

    const int t = threadIdx.x;
    const int q = blockIdx.x * 256 + t;
    const bool active = (q < n);

    if (active) {
        float4 X = SORTED ? g_sorted[q] : coords[q];
        float4* shr = reinterpret_cast<float4*>(sh + t * SH_STRIDE);
        #pragma unroll 1
        for (int k = 0; k < 8; ++k) {
            float a0, a1, b0, b1;
            encode_level(X, cfg.lv[2 * k],     tab, a0, a1);
            encode_level(X, cfg.lv[2 * k + 1], tab, b0, b1);
            shr[k] = make_float4(a0, a1, b0, b1);
        }
    }
    __syncthreads();

    // cooperative row-granular scattered writes: 8 lanes per 128B query row
    const int w = t >> 5, l = t & 31;
    const int f4 = l & 7;
    #pragma unroll 1
    for (int i = 0; i < 8; ++i) {
        int row = w * 32 + i * 4 + (l >> 3);
        int sq  = blockIdx.x * 256 + row;
        if (sq < n) {
            unsigned oq = SORTED ? g_oidx[sq] : (unsigned)sq;
            float4 v = reinterpret_cast<const float4*>(sh + row * SH_STRIDE)[f4];
            reinterpret_cast<float4*>(out + (size_t)oq * 32)[f4] = v;
        }
    }
}

// ---------------------------------------------------------------------------
// Host-side config: mirrors reference build_config() op-for-op in float64.
// ---------------------------------------------------------------------------
static KConfig build_cfg_host()
{
    const double minr[4] = {16.0, 16.0, 16.0, 16.0};
    const double maxr[4] = {256.0, 256.0, 256.0, 128.0};
    const long long MAXP = 524288; // 2^19

    double b[4];
    for (int d = 0; d < 4; ++d)
        b[d] = exp((log(maxr[d]) - log(minr[d])) / 15.0);

    KConfig cfg;
    long long total = 0;
    for (int s = 0; s < 16; ++s) {
        long long res[4];
        for (int d = 0; d < 4; ++d)
            res[d] = (long long)ceil(minr[d] * pow(b[d], (double)s));
        long long raw = (res[0] + 1) * (res[1] + 1) * (res[2] + 1) * (res[3] + 1);
        long long p = (raw % 8 == 0) ? raw : ((raw + 7) / 8) * 8;
        if (p > MAXP) p = MAXP;
        int dense = (raw <= p) ? 1 : 0;

        Level& L = cfg.lv[s];
        L.rf0 = (float)res[0]; L.rf1 = (float)res[1];
        L.rf2 = (float)res[2]; L.rf3 = (float)res[3];
        L.s1 = (unsigned)(res[0] + 1);
        L.s2 = (unsigned)((res[0] + 1) * (res[1] + 1));
        L.s3 = (unsigned)((res[0] + 1) * (res[1] + 1) * (res[2] + 1));
        L.size = (unsigned)p;
        L.mask = (unsigned)(p - 1);
        L.offset = (int)total;
        if (dense)                      L.mode = 0;
        else if ((p & (p - 1)) == 0)    L.mode = 1;
        else                            L.mode = 2;
        total += p * 2;  // F = 2
    }
    return cfg;
}

extern "C" void kernel_launch(void* const* d_in, const int* in_sizes, int n_in,
                              void* d_out, int out_size)
{
    static KConfig cfg = build_cfg_host();

    const float4* xyzt = (const float4*)d_in[0];
    const float*  tab  = (const float*)d_in[1];
    float*        out  = (float*)d_out;

    int n = in_sizes[0] / 4;
    int blocks = (n + 255) / 256;

    if (n <= CAP) {
        zero_hist_kernel<<<(NBINS + 1023) / 1024, 1024>>>();
        hist_kernel<<<blocks, 256>>>(xyzt, n);
        scan_kernel<<<1, 1024>>>();
        scatter_kernel<<<blocks, 256>>>(xyzt, n);
        hashenc_kernel<true><<<blocks, 256>>>(xyzt, tab, out, cfg, n);
    } else {
        hashenc_kernel<false><<<blocks, 256>>>(xyzt, tab, out, cfg, n);
    }
}

// round 6
// speedup vs baseline: 1.5973x; 1.5973x over previous
#include <cuda_runtime.h>
#include <math.h>
#include <stdint.h>

// ---------------------------------------------------------------------------
// HashEncoderHyFluid, R5: exact R2 encode structure (one level per loop iter,
// per-level float2 store, NO smem -> full 228KB L1D, ~40 regs) + Morton
// counting sort feeding it. Sorted lanes share grid cells at coarse levels ->
// gather wavefront broadcast. Output row index comes from g_oidx (store
// wavefront count identical to R2: 32 lines per STG.64 either way).
// ---------------------------------------------------------------------------

#define CAP   (1 << 20)
#define NBINS (1 << 18)     // 18-bit Morton key: x5 y5 z4 t4

__device__ float4   g_sorted[CAP];
__device__ unsigned g_oidx[CAP];
__device__ unsigned g_hist[NBINS];

struct Level {
    float    rf0, rf1, rf2, rf3;
    unsigned s1, s2, s3;           // dense strides
    unsigned mask;                 // size-1 (hashed pow2)
    unsigned size;
    int      offset;               // float offset into hash_table
    int      mode;                 // 0 dense, 1 hash+mask, 2 hash+mod
};
struct KConfig { Level lv[16]; };

#define HPRIME1 2654435761u
#define HPRIME2 805459861u
#define HPRIME3 3674653429u

// ---------------- sort kernels ----------------

__device__ __forceinline__ unsigned morton_key(float4 X)
{
    unsigned kx = (unsigned)(X.x * 32.f); if (kx > 31u) kx = 31u;
    unsigned ky = (unsigned)(X.y * 32.f); if (ky > 31u) ky = 31u;
    unsigned kz = (unsigned)(X.z * 16.f); if (kz > 15u) kz = 15u;
    unsigned kt = (unsigned)(X.w * 16.f); if (kt > 15u) kt = 15u;
    unsigned key = 0;
    #pragma unroll
    for (int b = 4; b >= 0; --b) {
        key = (key << 1) | ((kx >> b) & 1u);
        key = (key << 1) | ((ky >> b) & 1u);
        if (b < 4) {
            key = (key << 1) | ((kz >> b) & 1u);
            key = (key << 1) | ((kt >> b) & 1u);
        }
    }
    return key;   // 18 bits
}

__global__ void zero_hist_kernel()
{
    int i = blockIdx.x * blockDim.x + threadIdx.x;
    if (i < NBINS) g_hist[i] = 0u;
}

__global__ void hist_kernel(const float4* __restrict__ xyzt, int n)
{
    int i = blockIdx.x * blockDim.x + threadIdx.x;
    if (i >= n) return;
    atomicAdd(&g_hist[morton_key(xyzt[i])], 1u);
}

__global__ __launch_bounds__(1024)
void scan_kernel()
{
    __shared__ unsigned sh[1024];
    const int t = threadIdx.x;
    const int per = NBINS / 1024;
    const unsigned base = (unsigned)t * per;

    unsigned sum = 0;
    for (int i = 0; i < per; ++i) sum += g_hist[base + i];
    sh[t] = sum;
    __syncthreads();
    for (int off = 1; off < 1024; off <<= 1) {
        unsigned v = (t >= off) ? sh[t - off] : 0u;
        __syncthreads();
        sh[t] += v;
        __syncthreads();
    }
    unsigned run = sh[t] - sum;
    for (int i = 0; i < per; ++i) {
        unsigned h = g_hist[base + i];
        g_hist[base + i] = run;
        run += h;
    }
}

__global__ void scatter_kernel(const float4* __restrict__ xyzt, int n)
{
    int i = blockIdx.x * blockDim.x + threadIdx.x;
    if (i >= n) return;
    float4 X = xyzt[i];
    unsigned pos = atomicAdd(&g_hist[morton_key(X)], 1u);
    g_sorted[pos] = X;
    g_oidx[pos]   = (unsigned)i;
}

// ---------------- encode (R2 body, verbatim structure) ----------------

__device__ __forceinline__ void acc_pair128(const float2* __restrict__ t2,
                                            unsigned i0, float w0, float w1,
                                            float& a0, float& a1)
{
    unsigned m = i0 & ~1u;
    float4 f = __ldg(reinterpret_cast<const float4*>(t2 + m));
    bool odd = (i0 & 1u);
    float c0x = odd ? f.z : f.x, c0y = odd ? f.w : f.y;
    float c1x = odd ? f.x : f.z, c1y = odd ? f.y : f.w;
    a0 += w0 * c0x + w1 * c1x;
    a1 += w0 * c0y + w1 * c1y;
}

template <bool SORTED>
__global__ __launch_bounds__(256)
void hashenc_kernel(const float4* __restrict__ xyzt,
                    const float*  __restrict__ tab,
                    float*        __restrict__ out,
                    KConfig cfg, int n)
{
    int q = blockIdx.x * 256 + threadIdx.x;
    if (q >= n) return;

    float4 X = SORTED ? g_sorted[q] : xyzt[q];
    unsigned oq = SORTED ? g_oidx[q] : (unsigned)q;
    float2* outq = reinterpret_cast<float2*>(out + (size_t)oq * 32);

    #pragma unroll 1
    for (int s = 0; s < 16; ++s) {
        Level L = cfg.lv[s];

        float px = X.x * L.rf0, py = X.y * L.rf1, pz = X.z * L.rf2, pt = X.w * L.rf3;
        float gx = floorf(px),  gy = floorf(py),  gz = floorf(pz),  gt = floorf(pt);
        float fx = px - gx,     fy = py - gy,     fz = pz - gz,     ft = pt - gt;
        unsigned cx = (unsigned)(int)gx, cy = (unsigned)(int)gy;
        unsigned cz = (unsigned)(int)gz, ct = (unsigned)(int)gt;

        float wx0 = 1.f - fx, wy0 = 1.f - fy, wz0 = 1.f - fz, wt0 = 1.f - ft;
        float wxy[4], wzt[4];
        wxy[0] = wx0 * wy0;  wxy[1] = fx * wy0;  wxy[2] = wx0 * fy;  wxy[3] = fx * fy;
        wzt[0] = wz0 * wt0;  wzt[1] = fz * wt0;  wzt[2] = wz0 * ft;  wzt[3] = fz * ft;

        const float2* t2 = reinterpret_cast<const float2*>(tab) + (L.offset >> 1);
        float a0 = 0.f, a1 = 0.f;

        if (L.mode == 0) {
            unsigned bxy = cx + cy * L.s1;
            unsigned ixy0[2] = { bxy, bxy + L.s1 };
            unsigned bzt = cz * L.s2 + ct * L.s3;
            unsigned izt[4] = { bzt, bzt + L.s2, bzt + L.s3, bzt + L.s2 + L.s3 };
            #pragma unroll
            for (int j = 0; j < 4; ++j) {
                #pragma unroll
                for (int b = 0; b < 2; ++b) {
                    unsigned i0 = ixy0[b] + izt[j];
                    float w0 = wxy[2 * b]     * wzt[j];
                    float w1 = wxy[2 * b + 1] * wzt[j];
                    if ((i0 & 1u) == 0u) {
                        acc_pair128(t2, i0, w0, w1, a0, a1);
                    } else {
                        float2 f0 = __ldg(t2 + i0);
                        float2 f1 = __ldg(t2 + i0 + 1u);
                        a0 += w0 * f0.x + w1 * f1.x;
                        a1 += w0 * f0.y + w1 * f1.y;
                    }
                }
            }
        } else {
            unsigned hy = cy * HPRIME1, hz = cz * HPRIME2, ht = ct * HPRIME3;
            unsigned msk = L.mask;
            unsigned rxy0[2] = { hy, hy + HPRIME1 };
            unsigned izt[4] = { hz ^ ht, (hz + HPRIME2) ^ ht,
                                hz ^ (ht + HPRIME3), (hz + HPRIME2) ^ (ht + HPRIME3) };
            if (L.mode == 1) {
                if ((cx & 1u) == 0u) {
                    #pragma unroll
                    for (int j = 0; j < 4; ++j) {
                        #pragma unroll
                        for (int b = 0; b < 2; ++b) {
                            unsigned i0 = (cx ^ rxy0[b] ^ izt[j]) & msk;
                            acc_pair128(t2, i0,
                                        wxy[2 * b] * wzt[j], wxy[2 * b + 1] * wzt[j],
                                        a0, a1);
                        }
                    }
                } else {
                    unsigned cx1 = cx + 1u;
                    #pragma unroll
                    for (int j = 0; j < 4; ++j) {
                        #pragma unroll
                        for (int b = 0; b < 2; ++b) {
                            unsigned r = rxy0[b] ^ izt[j];
                            unsigned i0 = (cx  ^ r) & msk;
                            unsigned i1 = (cx1 ^ r) & msk;
                            float w0 = wxy[2 * b]     * wzt[j];
                            float w1 = wxy[2 * b + 1] * wzt[j];
                            float2 f0 = __ldg(t2 + i0);
                            float2 f1 = __ldg(t2 + i1);
                            a0 += w0 * f0.x + w1 * f1.x;
                            a1 += w0 * f0.y + w1 * f1.y;
                        }
                    }
                }
            } else {
                unsigned sz = L.size, cx1 = cx + 1u;
                #pragma unroll
                for (int j = 0; j < 4; ++j) {
                    #pragma unroll
                    for (int b = 0; b < 2; ++b) {
                        unsigned r = rxy0[b] ^ izt[j];
                        unsigned i0 = (cx  ^ r) % sz;
                        unsigned i1 = (cx1 ^ r) % sz;
                        float w0 = wxy[2 * b]     * wzt[j];
                        float w1 = wxy[2 * b + 1] * wzt[j];
                        float2 f0 = __ldg(t2 + i0);
                        float2 f1 = __ldg(t2 + i1);
                        a0 += w0 * f0.x + w1 * f1.x;
                        a1 += w0 * f0.y + w1 * f1.y;
                    }
                }
            }
        }
        *outq = make_float2(a0, a1);
        ++outq;
    }
}

// ---------------------------------------------------------------------------
// Host-side config: mirrors reference build_config() op-for-op in float64.
// ---------------------------------------------------------------------------
static KConfig build_cfg_host()
{
    const double minr[4] = {16.0, 16.0, 16.0, 16.0};
    const double maxr[4] = {256.0, 256.0, 256.0, 128.0};
    const long long MAXP = 524288; // 2^19

    double b[4];
    for (int d = 0; d < 4; ++d)
        b[d] = exp((log(maxr[d]) - log(minr[d])) / 15.0);

    KConfig cfg;
    long long total = 0;
    for (int s = 0; s < 16; ++s) {
        long long res[4];
        for (int d = 0; d < 4; ++d)
            res[d] = (long long)ceil(minr[d] * pow(b[d], (double)s));
        long long raw = (res[0] + 1) * (res[1] + 1) * (res[2] + 1) * (res[3] + 1);
        long long p = (raw % 8 == 0) ? raw : ((raw + 7) / 8) * 8;
        if (p > MAXP) p = MAXP;
        int dense = (raw <= p) ? 1 : 0;

        Level& L = cfg.lv[s];
        L.rf0 = (float)res[0]; L.rf1 = (float)res[1];
        L.rf2 = (float)res[2]; L.rf3 = (float)res[3];
        L.s1 = (unsigned)(res[0] + 1);
        L.s2 = (unsigned)((res[0] + 1) * (res[1] + 1));
        L.s3 = (unsigned)((res[0] + 1) * (res[1] + 1) * (res[2] + 1));
        L.size = (unsigned)p;
        L.mask = (unsigned)(p - 1);
        L.offset = (int)total;
        if (dense)                      L.mode = 0;
        else if ((p & (p - 1)) == 0)    L.mode = 1;
        else                            L.mode = 2;
        total += p * 2;  // F = 2
    }
    return cfg;
}

extern "C" void kernel_launch(void* const* d_in, const int* in_sizes, int n_in,
                              void* d_out, int out_size)
{
    static KConfig cfg = build_cfg_host();

    const float4* xyzt = (const float4*)d_in[0];
    const float*  tab  = (const float*)d_in[1];
    float*        out  = (float*)d_out;

    int n = in_sizes[0] / 4;
    int blocks = (n + 255) / 256;

    if (n <= CAP) {
        zero_hist_kernel<<<(NBINS + 1023) / 1024, 1024>>>();
        hist_kernel<<<blocks, 256>>>(xyzt, n);
        scan_kernel<<<1, 1024>>>();
        scatter_kernel<<<blocks, 256>>>(xyzt, n);
        hashenc_kernel<true><<<blocks, 256>>>(xyzt, tab, out, cfg, n);
    } else {
        hashenc_kernel<false><<<blocks, 256>>>(xyzt, tab, out, cfg, n);
    }
}

// round 7
// speedup vs baseline: 2.2408x; 1.4029x over previous
#include <cuda_runtime.h>
#include <math.h>
#include <stdint.h>

// ---------------------------------------------------------------------------
// HashEncoderHyFluid, R6: R2 structure (best: 639us) + ld.global.cg (L2-only,
// no L1 allocate) for the 13 hashed levels. Hashed gathers hit ~4MB random
// regions -> ~80% L1 miss; default policy burns an L1tex fill wavefront per
// miss for data that is never reused. .cg removes the fill work and stops
// hash traffic from thrashing the dense levels' L1 lines. Sort pipeline from
// R3-R5 removed (empirically a consistent loss).
// ---------------------------------------------------------------------------

struct Level {
    float    rf0, rf1, rf2, rf3;   // res as float32
    unsigned s1, s2, s3;           // dense strides
    unsigned mask;                 // size-1 (hashed pow2)
    unsigned size;
    int      offset;               // float offset into hash_table
    int      mode;                 // 0 dense, 1 hash+mask, 2 hash+mod
};
struct KConfig { Level lv[16]; };

#define HPRIME1 2654435761u
#define HPRIME2 805459861u
#define HPRIME3 3674653429u

// L2-cached, L1-bypass loads for hash-level gathers
__device__ __forceinline__ float4 ldcg_f4(const float4* p)
{
    float4 v;
    asm("ld.global.cg.v4.f32 {%0,%1,%2,%3}, [%4];"
        : "=f"(v.x), "=f"(v.y), "=f"(v.z), "=f"(v.w) : "l"(p));
    return v;
}
__device__ __forceinline__ float2 ldcg_f2(const float2* p)
{
    float2 v;
    asm("ld.global.cg.v2.f32 {%0,%1}, [%2];"
        : "=f"(v.x), "=f"(v.y) : "l"(p));
    return v;
}

// accumulate an x-pair from one aligned float4 covering entries {m, m+1}
template <bool CG>
__device__ __forceinline__ void acc_pair128(const float2* __restrict__ t2,
                                            unsigned i0, float w0, float w1,
                                            float& a0, float& a1)
{
    unsigned m = i0 & ~1u;
    const float4* p = reinterpret_cast<const float4*>(t2 + m);
    float4 f = CG ? ldcg_f4(p) : __ldg(p);
    bool odd = (i0 & 1u);
    float c0x = odd ? f.z : f.x, c0y = odd ? f.w : f.y;
    float c1x = odd ? f.x : f.z, c1y = odd ? f.y : f.w;
    a0 += w0 * c0x + w1 * c1x;
    a1 += w0 * c0y + w1 * c1y;
}

__global__ __launch_bounds__(256)
void hashenc_kernel(const float4* __restrict__ xyzt,
                    const float*  __restrict__ tab,
                    float*        __restrict__ out,
                    KConfig cfg, int n)
{
    int q = blockIdx.x * 256 + threadIdx.x;
    if (q >= n) return;

    float4 X = xyzt[q];
    float2* outq = reinterpret_cast<float2*>(out + (size_t)q * 32);

    #pragma unroll 1
    for (int s = 0; s < 16; ++s) {
        Level L = cfg.lv[s];

        float px = X.x * L.rf0, py = X.y * L.rf1, pz = X.z * L.rf2, pt = X.w * L.rf3;
        float gx = floorf(px),  gy = floorf(py),  gz = floorf(pz),  gt = floorf(pt);
        float fx = px - gx,     fy = py - gy,     fz = pz - gz,     ft = pt - gt;
        unsigned cx = (unsigned)(int)gx, cy = (unsigned)(int)gy;
        unsigned cz = (unsigned)(int)gz, ct = (unsigned)(int)gt;

        float wx0 = 1.f - fx, wy0 = 1.f - fy, wz0 = 1.f - fz, wt0 = 1.f - ft;
        float wxy[4], wzt[4];
        wxy[0] = wx0 * wy0;  wxy[1] = fx * wy0;  wxy[2] = wx0 * fy;  wxy[3] = fx * fy;
        wzt[0] = wz0 * wt0;  wzt[1] = fz * wt0;  wzt[2] = wz0 * ft;  wzt[3] = fz * ft;

        const float2* t2 = reinterpret_cast<const float2*>(tab) + (L.offset >> 1);
        float a0 = 0.f, a1 = 0.f;

        if (L.mode == 0) {
            // dense small tables: keep L1-cached loads (reuse-friendly)
            unsigned bxy = cx + cy * L.s1;
            unsigned ixy0[2] = { bxy, bxy + L.s1 };
            unsigned bzt = cz * L.s2 + ct * L.s3;
            unsigned izt[4] = { bzt, bzt + L.s2, bzt + L.s3, bzt + L.s2 + L.s3 };
            #pragma unroll
            for (int j = 0; j < 4; ++j) {
                #pragma unroll
                for (int b = 0; b < 2; ++b) {
                    unsigned i0 = ixy0[b] + izt[j];
                    float w0 = wxy[2 * b]     * wzt[j];
                    float w1 = wxy[2 * b + 1] * wzt[j];
                    if ((i0 & 1u) == 0u) {
                        acc_pair128<false>(t2, i0, w0, w1, a0, a1);
                    } else {
                        float2 f0 = __ldg(t2 + i0);
                        float2 f1 = __ldg(t2 + i0 + 1u);
                        a0 += w0 * f0.x + w1 * f1.x;
                        a1 += w0 * f0.y + w1 * f1.y;
                    }
                }
            }
        } else {
            // hashed levels: L1-bypass gathers
            unsigned hy = cy * HPRIME1, hz = cz * HPRIME2, ht = ct * HPRIME3;
            unsigned msk = L.mask;
            unsigned rxy0[2] = { hy, hy + HPRIME1 };
            unsigned izt[4] = { hz ^ ht, (hz + HPRIME2) ^ ht,
                                hz ^ (ht + HPRIME3), (hz + HPRIME2) ^ (ht + HPRIME3) };
            if (L.mode == 1) {
                if ((cx & 1u) == 0u) {
                    #pragma unroll
                    for (int j = 0; j < 4; ++j) {
                        #pragma unroll
                        for (int b = 0; b < 2; ++b) {
                            unsigned i0 = (cx ^ rxy0[b] ^ izt[j]) & msk;
                            acc_pair128<true>(t2, i0,
                                              wxy[2 * b] * wzt[j], wxy[2 * b + 1] * wzt[j],
                                              a0, a1);
                        }
                    }
                } else {
                    unsigned cx1 = cx + 1u;
                    #pragma unroll
                    for (int j = 0; j < 4; ++j) {
                        #pragma unroll
                        for (int b = 0; b < 2; ++b) {
                            unsigned r = rxy0[b] ^ izt[j];
                            unsigned i0 = (cx  ^ r) & msk;
                            unsigned i1 = (cx1 ^ r) & msk;
                            float w0 = wxy[2 * b]     * wzt[j];
                            float w1 = wxy[2 * b + 1] * wzt[j];
                            float2 f0 = ldcg_f2(t2 + i0);
                            float2 f1 = ldcg_f2(t2 + i1);
                            a0 += w0 * f0.x + w1 * f1.x;
                            a1 += w0 * f0.y + w1 * f1.y;
                        }
                    }
                }
            } else {
                // generic mod fallback (never taken with current constants)
                unsigned sz = L.size, cx1 = cx + 1u;
                #pragma unroll
                for (int j = 0; j < 4; ++j) {
                    #pragma unroll
                    for (int b = 0; b < 2; ++b) {
                        unsigned r = rxy0[b] ^ izt[j];
                        unsigned i0 = (cx  ^ r) % sz;
                        unsigned i1 = (cx1 ^ r) % sz;
                        float w0 = wxy[2 * b]     * wzt[j];
                        float w1 = wxy[2 * b + 1] * wzt[j];
                        float2 f0 = ldcg_f2(t2 + i0);
                        float2 f1 = ldcg_f2(t2 + i1);
                        a0 += w0 * f0.x + w1 * f1.x;
                        a1 += w0 * f0.y + w1 * f1.y;
                    }
                }
            }
        }
        *outq = make_float2(a0, a1);
        ++outq;
    }
}

// ---------------------------------------------------------------------------
// Host-side config: mirrors reference build_config() op-for-op in float64.
// ---------------------------------------------------------------------------
static KConfig build_cfg_host()
{
    const double minr[4] = {16.0, 16.0, 16.0, 16.0};
    const double maxr[4] = {256.0, 256.0, 256.0, 128.0};
    const long long MAXP = 524288; // 2^19

    double b[4];
    for (int d = 0; d < 4; ++d)
        b[d] = exp((log(maxr[d]) - log(minr[d])) / 15.0);

    KConfig cfg;
    long long total = 0;
    for (int s = 0; s < 16; ++s) {
        long long res[4];
        for (int d = 0; d < 4; ++d)
            res[d] = (long long)ceil(minr[d] * pow(b[d], (double)s));
        long long raw = (res[0] + 1) * (res[1] + 1) * (res[2] + 1) * (res[3] + 1);
        long long p = (raw % 8 == 0) ? raw : ((raw + 7) / 8) * 8;
        if (p > MAXP) p = MAXP;
        int dense = (raw <= p) ? 1 : 0;

        Level& L = cfg.lv[s];
        L.rf0 = (float)res[0]; L.rf1 = (float)res[1];
        L.rf2 = (float)res[2]; L.rf3 = (float)res[3];
        L.s1 = (unsigned)(res[0] + 1);
        L.s2 = (unsigned)((res[0] + 1) * (res[1] + 1));
        L.s3 = (unsigned)((res[0] + 1) * (res[1] + 1) * (res[2] + 1));
        L.size = (unsigned)p;
        L.mask = (unsigned)(p - 1);
        L.offset = (int)total;
        if (dense)                      L.mode = 0;
        else if ((p & (p - 1)) == 0)    L.mode = 1;
        else                            L.mode = 2;
        total += p * 2;  // F = 2
    }
    return cfg;
}

extern "C" void kernel_launch(void* const* d_in, const int* in_sizes, int n_in,
                              void* d_out, int out_size)
{
    static KConfig cfg = build_cfg_host();

    const float4* xyzt = (const float4*)d_in[0];
    const float*  tab  = (const float*)d_in[1];
    float*        out  = (float*)d_out;

    int n = in_sizes[0] / 4;
    int blocks = (n + 255) / 256;
    hashenc_kernel<<<blocks, 256>>>(xyzt, tab, out, cfg, n);
}

// round 8
// speedup vs baseline: 2.5137x; 1.1218x over previous
#include <cuda_runtime.h>
#include <math.h>
#include <stdint.h>

// ---------------------------------------------------------------------------
// HashEncoderHyFluid, R7: R2 encode body (best known: 639us), but each thread
// processes TWO queries (q and q+n/2). Level constants are shared across both
// gather chains; two independent dependency chains double per-warp load MLP
// and fill the L1tex pipe (R2 measured 89.6% util at the wavefront floor).
// Wavefront count is unchanged; this targets the last ~10% of pipe idle.
// ---------------------------------------------------------------------------

struct Level {
    float    rf0, rf1, rf2, rf3;   // res as float32
    unsigned s1, s2, s3;           // dense strides
    unsigned mask;                 // size-1 (hashed pow2)
    unsigned size;
    int      offset;               // float offset into hash_table
    int      mode;                 // 0 dense, 1 hash+mask, 2 hash+mod
};
struct KConfig { Level lv[16]; };

#define HPRIME1 2654435761u
#define HPRIME2 805459861u
#define HPRIME3 3674653429u

__device__ __forceinline__ void acc_pair128(const float2* __restrict__ t2,
                                            unsigned i0, float w0, float w1,
                                            float& a0, float& a1)
{
    unsigned m = i0 & ~1u;
    float4 f = __ldg(reinterpret_cast<const float4*>(t2 + m));
    bool odd = (i0 & 1u);
    float c0x = odd ? f.z : f.x, c0y = odd ? f.w : f.y;
    float c1x = odd ? f.x : f.z, c1y = odd ? f.y : f.w;
    a0 += w0 * c0x + w1 * c1x;
    a1 += w0 * c0y + w1 * c1y;
}

// one query, one level (R2 body verbatim)
__device__ __forceinline__ void enc1(const float4& X, const Level& L,
                                     const float* __restrict__ tab,
                                     float& a0, float& a1)
{
    float px = X.x * L.rf0, py = X.y * L.rf1, pz = X.z * L.rf2, pt = X.w * L.rf3;
    float gx = floorf(px),  gy = floorf(py),  gz = floorf(pz),  gt = floorf(pt);
    float fx = px - gx,     fy = py - gy,     fz = pz - gz,     ft = pt - gt;
    unsigned cx = (unsigned)(int)gx, cy = (unsigned)(int)gy;
    unsigned cz = (unsigned)(int)gz, ct = (unsigned)(int)gt;

    float wx0 = 1.f - fx, wy0 = 1.f - fy, wz0 = 1.f - fz, wt0 = 1.f - ft;
    float wxy[4], wzt[4];
    wxy[0] = wx0 * wy0;  wxy[1] = fx * wy0;  wxy[2] = wx0 * fy;  wxy[3] = fx * fy;
    wzt[0] = wz0 * wt0;  wzt[1] = fz * wt0;  wzt[2] = wz0 * ft;  wzt[3] = fz * ft;

    const float2* t2 = reinterpret_cast<const float2*>(tab) + (L.offset >> 1);
    a0 = 0.f; a1 = 0.f;

    if (L.mode == 0) {
        unsigned bxy = cx + cy * L.s1;
        unsigned ixy0[2] = { bxy, bxy + L.s1 };
        unsigned bzt = cz * L.s2 + ct * L.s3;
        unsigned izt[4] = { bzt, bzt + L.s2, bzt + L.s3, bzt + L.s2 + L.s3 };
        #pragma unroll
        for (int j = 0; j < 4; ++j) {
            #pragma unroll
            for (int b = 0; b < 2; ++b) {
                unsigned i0 = ixy0[b] + izt[j];
                float w0 = wxy[2 * b]     * wzt[j];
                float w1 = wxy[2 * b + 1] * wzt[j];
                if ((i0 & 1u) == 0u) {
                    acc_pair128(t2, i0, w0, w1, a0, a1);
                } else {
                    float2 f0 = __ldg(t2 + i0);
                    float2 f1 = __ldg(t2 + i0 + 1u);
                    a0 += w0 * f0.x + w1 * f1.x;
                    a1 += w0 * f0.y + w1 * f1.y;
                }
            }
        }
    } else {
        unsigned hy = cy * HPRIME1, hz = cz * HPRIME2, ht = ct * HPRIME3;
        unsigned msk = L.mask;
        unsigned rxy0[2] = { hy, hy + HPRIME1 };
        unsigned izt[4] = { hz ^ ht, (hz + HPRIME2) ^ ht,
                            hz ^ (ht + HPRIME3), (hz + HPRIME2) ^ (ht + HPRIME3) };
        if (L.mode == 1) {
            if ((cx & 1u) == 0u) {
                #pragma unroll
                for (int j = 0; j < 4; ++j) {
                    #pragma unroll
                    for (int b = 0; b < 2; ++b) {
                        unsigned i0 = (cx ^ rxy0[b] ^ izt[j]) & msk;
                        acc_pair128(t2, i0,
                                    wxy[2 * b] * wzt[j], wxy[2 * b + 1] * wzt[j],
                                    a0, a1);
                    }
                }
            } else {
                unsigned cx1 = cx + 1u;
                #pragma unroll
                for (int j = 0; j < 4; ++j) {
                    #pragma unroll
                    for (int b = 0; b < 2; ++b) {
                        unsigned r = rxy0[b] ^ izt[j];
                        unsigned i0 = (cx  ^ r) & msk;
                        unsigned i1 = (cx1 ^ r) & msk;
                        float w0 = wxy[2 * b]     * wzt[j];
                        float w1 = wxy[2 * b + 1] * wzt[j];
                        float2 f0 = __ldg(t2 + i0);
                        float2 f1 = __ldg(t2 + i1);
                        a0 += w0 * f0.x + w1 * f1.x;
                        a1 += w0 * f0.y + w1 * f1.y;
                    }
                }
            }
        } else {
            unsigned sz = L.size, cx1 = cx + 1u;
            #pragma unroll
            for (int j = 0; j < 4; ++j) {
                #pragma unroll
                for (int b = 0; b < 2; ++b) {
                    unsigned r = rxy0[b] ^ izt[j];
                    unsigned i0 = (cx  ^ r) % sz;
                    unsigned i1 = (cx1 ^ r) % sz;
                    float w0 = wxy[2 * b]     * wzt[j];
                    float w1 = wxy[2 * b + 1] * wzt[j];
                    float2 f0 = __ldg(t2 + i0);
                    float2 f1 = __ldg(t2 + i1);
                    a0 += w0 * f0.x + w1 * f1.x;
                    a1 += w0 * f0.y + w1 * f1.y;
                }
            }
        }
    }
}

__global__ __launch_bounds__(256)
void hashenc_kernel(const float4* __restrict__ xyzt,
                    const float*  __restrict__ tab,
                    float*        __restrict__ out,
                    KConfig cfg, int n, int nh)
{
    int q0 = blockIdx.x * 256 + threadIdx.x;
    if (q0 >= nh) return;
    int q1 = q0 + nh;
    bool has2 = (q1 < n);

    float4 X0 = __ldg(&xyzt[q0]);
    float4 X1 = has2 ? __ldg(&xyzt[q1]) : X0;

    float2* o0 = reinterpret_cast<float2*>(out + (size_t)q0 * 32);
    float2* o1 = reinterpret_cast<float2*>(out + (size_t)q1 * 32);

    #pragma unroll 1
    for (int s = 0; s < 16; ++s) {
        Level L = cfg.lv[s];
        float a0, a1, b0, b1;
        enc1(X0, L, tab, a0, a1);
        enc1(X1, L, tab, b0, b1);
        o0[s] = make_float2(a0, a1);
        if (has2) o1[s] = make_float2(b0, b1);
    }
}

// ---------------------------------------------------------------------------
// Host-side config: mirrors reference build_config() op-for-op in float64.
// ---------------------------------------------------------------------------
static KConfig build_cfg_host()
{
    const double minr[4] = {16.0, 16.0, 16.0, 16.0};
    const double maxr[4] = {256.0, 256.0, 256.0, 128.0};
    const long long MAXP = 524288; // 2^19

    double b[4];
    for (int d = 0; d < 4; ++d)
        b[d] = exp((log(maxr[d]) - log(minr[d])) / 15.0);

    KConfig cfg;
    long long total = 0;
    for (int s = 0; s < 16; ++s) {
        long long res[4];
        for (int d = 0; d < 4; ++d)
            res[d] = (long long)ceil(minr[d] * pow(b[d], (double)s));
        long long raw = (res[0] + 1) * (res[1] + 1) * (res[2] + 1) * (res[3] + 1);
        long long p = (raw % 8 == 0) ? raw : ((raw + 7) / 8) * 8;
        if (p > MAXP) p = MAXP;
        int dense = (raw <= p) ? 1 : 0;

        Level& L = cfg.lv[s];
        L.rf0 = (float)res[0]; L.rf1 = (float)res[1];
        L.rf2 = (float)res[2]; L.rf3 = (float)res[3];
        L.s1 = (unsigned)(res[0] + 1);
        L.s2 = (unsigned)((res[0] + 1) * (res[1] + 1));
        L.s3 = (unsigned)((res[0] + 1) * (res[1] + 1) * (res[2] + 1));
        L.size = (unsigned)p;
        L.mask = (unsigned)(p - 1);
        L.offset = (int)total;
        if (dense)                      L.mode = 0;
        else if ((p & (p - 1)) == 0)    L.mode = 1;
        else                            L.mode = 2;
        total += p * 2;  // F = 2
    }
    return cfg;
}

extern "C" void kernel_launch(void* const* d_in, const int* in_sizes, int n_in,
                              void* d_out, int out_size)
{
    static KConfig cfg = build_cfg_host();

    const float4* xyzt = (const float4*)d_in[0];
    const float*  tab  = (const float*)d_in[1];
    float*        out  = (float*)d_out;

    int n  = in_sizes[0] / 4;
    int nh = (n + 1) / 2;
    int blocks = (nh + 255) / 256;
    hashenc_kernel<<<blocks, 256>>>(xyzt, tab, out, cfg, n, nh);
}

// round 9
// speedup vs baseline: 2.9198x; 1.1615x over previous
#include <cuda_runtime.h>
#include <math.h>
#include <stdint.h>

// ---------------------------------------------------------------------------
// HashEncoderHyFluid, R8: lane-pair cooperative gathers.
// Two lanes per query: lane 2p -> x-corner bit 0, lane 2p+1 -> x-corner bit 1.
// Since PRIMES[0]==1, the pair's hashed indices differ by cx^(cx+1) (a low-bit
// mask), so both addresses fall in the same 128B line with prob ~15/16 (dense:
// i0,i0+1, same line 15/16). Issued in the SAME LDG.64 instruction they
// coalesce to ONE L1tex wavefront -> ~8.5 line-accesses/query/level vs 12 for
// the per-thread scheme (-29%), uniformly (no parity divergence at all).
// Partial sums combine via shfl_xor(1); even lane stores the float2.
// ---------------------------------------------------------------------------

struct Level {
    float    rf0, rf1, rf2, rf3;   // res as float32
    unsigned s1, s2, s3;           // dense strides
    unsigned mask;                 // size-1 (hashed pow2)
    unsigned size;
    int      offset;               // float offset into hash_table
    int      mode;                 // 0 dense, 1 hash+mask, 2 hash+mod
};
struct KConfig { Level lv[16]; };

#define HPRIME1 2654435761u
#define HPRIME2 805459861u
#define HPRIME3 3674653429u

__global__ __launch_bounds__(256)
void hashenc_kernel(const float4* __restrict__ xyzt,
                    const float*  __restrict__ tab,
                    float*        __restrict__ out,
                    KConfig cfg, int n)
{
    int tid = blockIdx.x * 256 + threadIdx.x;
    int q = tid >> 1;              // two lanes per query
    if (q >= n) return;
    const unsigned xb = (unsigned)(tid & 1);
    const unsigned amask = __activemask();   // pair lanes exit together

    float4 X = __ldg(&xyzt[q]);
    float2* outq = reinterpret_cast<float2*>(out + (size_t)q * 32);

    #pragma unroll 1
    for (int s = 0; s < 16; ++s) {
        Level L = cfg.lv[s];

        float px = X.x * L.rf0, py = X.y * L.rf1, pz = X.z * L.rf2, pt = X.w * L.rf3;
        float gx = floorf(px),  gy = floorf(py),  gz = floorf(pz),  gt = floorf(pt);
        float fx = px - gx,     fy = py - gy,     fz = pz - gz,     ft = pt - gt;
        unsigned cx = (unsigned)(int)gx, cy = (unsigned)(int)gy;
        unsigned cz = (unsigned)(int)gz, ct = (unsigned)(int)gt;

        // this lane's x-weight; 8 (y,z,t) corner weights
        float wxs = xb ? fx : (1.f - fx);
        float wy0 = 1.f - fy, wz0 = 1.f - fz, wt0 = 1.f - ft;
        float wzt[4];
        wzt[0] = wz0 * wt0;  wzt[1] = fz * wt0;  wzt[2] = wz0 * ft;  wzt[3] = fz * ft;
        float wj[8];
        #pragma unroll
        for (int k = 0; k < 4; ++k) { wj[k] = wy0 * wzt[k]; wj[4 + k] = fy * wzt[k]; }

        // 8 table indices for this lane's x-corner
        unsigned bx = cx + xb;
        unsigned idx[8];
        if (L.mode == 0) {
            unsigned base0 = bx + cy * L.s1 + cz * L.s2 + ct * L.s3;
            idx[0] = base0;
            idx[1] = base0 + L.s2;
            idx[2] = base0 + L.s3;
            idx[3] = base0 + L.s2 + L.s3;
            #pragma unroll
            for (int k = 0; k < 4; ++k) idx[4 + k] = idx[k] + L.s1;
        } else if (L.mode == 1) {
            unsigned hy = cy * HPRIME1, hz = cz * HPRIME2, ht = ct * HPRIME3;
            unsigned msk = L.mask;
            unsigned rzt[4] = { hz ^ ht, (hz + HPRIME2) ^ ht,
                                hz ^ (ht + HPRIME3), (hz + HPRIME2) ^ (ht + HPRIME3) };
            #pragma unroll
            for (int k = 0; k < 4; ++k) {
                idx[k]     = (bx ^ hy             ^ rzt[k]) & msk;
                idx[4 + k] = (bx ^ (hy + HPRIME1) ^ rzt[k]) & msk;
            }
        } else {
            // generic mod fallback (never taken with current constants)
            unsigned hy = cy * HPRIME1, hz = cz * HPRIME2, ht = ct * HPRIME3;
            unsigned sz = L.size;
            unsigned rzt[4] = { hz ^ ht, (hz + HPRIME2) ^ ht,
                                hz ^ (ht + HPRIME3), (hz + HPRIME2) ^ (ht + HPRIME3) };
            #pragma unroll
            for (int k = 0; k < 4; ++k) {
                idx[k]     = (bx ^ hy             ^ rzt[k]) % sz;
                idx[4 + k] = (bx ^ (hy + HPRIME1) ^ rzt[k]) % sz;
            }
        }

        const float2* t2 = reinterpret_cast<const float2*>(tab) + (L.offset >> 1);
        float a0 = 0.f, a1 = 0.f;
        #pragma unroll
        for (int k = 0; k < 8; ++k) {
            float2 f = __ldg(t2 + idx[k]);    // pair lanes hit the same 128B line
            a0 += wj[k] * f.x;
            a1 += wj[k] * f.y;
        }
        a0 *= wxs;
        a1 *= wxs;
        a0 += __shfl_xor_sync(amask, a0, 1);
        a1 += __shfl_xor_sync(amask, a1, 1);
        if (xb == 0u) outq[s] = make_float2(a0, a1);
    }
}

// ---------------------------------------------------------------------------
// Host-side config: mirrors reference build_config() op-for-op in float64.
// ---------------------------------------------------------------------------
static KConfig build_cfg_host()
{
    const double minr[4] = {16.0, 16.0, 16.0, 16.0};
    const double maxr[4] = {256.0, 256.0, 256.0, 128.0};
    const long long MAXP = 524288; // 2^19

    double b[4];
    for (int d = 0; d < 4; ++d)
        b[d] = exp((log(maxr[d]) - log(minr[d])) / 15.0);

    KConfig cfg;
    long long total = 0;
    for (int s = 0; s < 16; ++s) {
        long long res[4];
        for (int d = 0; d < 4; ++d)
            res[d] = (long long)ceil(minr[d] * pow(b[d], (double)s));
        long long raw = (res[0] + 1) * (res[1] + 1) * (res[2] + 1) * (res[3] + 1);
        long long p = (raw % 8 == 0) ? raw : ((raw + 7) / 8) * 8;
        if (p > MAXP) p = MAXP;
        int dense = (raw <= p) ? 1 : 0;

        Level& L = cfg.lv[s];
        L.rf0 = (float)res[0]; L.rf1 = (float)res[1];
        L.rf2 = (float)res[2]; L.rf3 = (float)res[3];
        L.s1 = (unsigned)(res[0] + 1);
        L.s2 = (unsigned)((res[0] + 1) * (res[1] + 1));
        L.s3 = (unsigned)((res[0] + 1) * (res[1] + 1) * (res[2] + 1));
        L.size = (unsigned)p;
        L.mask = (unsigned)(p - 1);
        L.offset = (int)total;
        if (dense)                      L.mode = 0;
        else if ((p & (p - 1)) == 0)    L.mode = 1;
        else                            L.mode = 2;
        total += p * 2;  // F = 2
    }
    return cfg;
}

extern "C" void kernel_launch(void* const* d_in, const int* in_sizes, int n_in,
                              void* d_out, int out_size)
{
    static KConfig cfg = build_cfg_host();

    const float4* xyzt = (const float4*)d_in[0];
    const float*  tab  = (const float*)d_in[1];
    float*        out  = (float*)d_out;

    int n = in_sizes[0] / 4;
    long long threads = 2LL * n;
    int blocks = (int)((threads + 255) / 256);
    hashenc_kernel<<<blocks, 256>>>(xyzt, tab, out, cfg, n);
}

// round 11
// speedup vs baseline: 3.3683x; 1.1536x over previous
#include <cuda_runtime.h>
#include <math.h>
#include <stdint.h>

// ---------------------------------------------------------------------------
// HashEncoderHyFluid, R9: R8 lane-pair cooperative gathers (541us) + batched
// coalesced stores. After the per-level shfl_xor both pair lanes hold the
// level result; buffering 4 levels lets the two lanes issue STG.128s into the
// same 128B output row in one instruction -> 1 store wavefront per query per
// 4 levels (was 16 STG.64 line-accesses per query). -12M wavefronts total.
// ---------------------------------------------------------------------------

struct Level {
    float    rf0, rf1, rf2, rf3;   // res as float32
    unsigned s1, s2, s3;           // dense strides
    unsigned mask;                 // size-1 (hashed pow2)
    unsigned size;
    int      offset;               // float offset into hash_table
    int      mode;                 // 0 dense, 1 hash+mask, 2 hash+mod
};
struct KConfig { Level lv[16]; };

#define HPRIME1 2654435761u
#define HPRIME2 805459861u
#define HPRIME3 3674653429u

__global__ __launch_bounds__(256)
void hashenc_kernel(const float4* __restrict__ xyzt,
                    const float*  __restrict__ tab,
                    float*        __restrict__ out,
                    KConfig cfg, int n)
{
    int tid = blockIdx.x * 256 + threadIdx.x;
    int q = tid >> 1;              // two lanes per query
    if (q >= n) return;
    const unsigned xb = (unsigned)(tid & 1);
    const unsigned amask = __activemask();   // pair lanes exit together

    float4 X = __ldg(&xyzt[q]);
    // output row = 8 float4 slots; 4-level group g: even lane writes slot 2g
    // (levels 4g,4g+1), odd lane slot 2g+1 (levels 4g+2,4g+3) -> same line.
    float4* orow = reinterpret_cast<float4*>(out + (size_t)q * 32);

    float r0 = 0.f, r1 = 0.f, r2 = 0.f, r3 = 0.f;   // 2 buffered level results

    #pragma unroll 1
    for (int s = 0; s < 16; ++s) {
        Level L = cfg.lv[s];

        float px = X.x * L.rf0, py = X.y * L.rf1, pz = X.z * L.rf2, pt = X.w * L.rf3;
        float gx = floorf(px),  gy = floorf(py),  gz = floorf(pz),  gt = floorf(pt);
        float fx = px - gx,     fy = py - gy,     fz = pz - gz,     ft = pt - gt;
        unsigned cx = (unsigned)(int)gx, cy = (unsigned)(int)gy;
        unsigned cz = (unsigned)(int)gz, ct = (unsigned)(int)gt;

        // this lane's x-weight; 8 (y,z,t) corner weights
        float wxs = xb ? fx : (1.f - fx);
        float wy0 = 1.f - fy, wz0 = 1.f - fz, wt0 = 1.f - ft;
        float wzt[4];
        wzt[0] = wz0 * wt0;  wzt[1] = fz * wt0;  wzt[2] = wz0 * ft;  wzt[3] = fz * ft;
        float wj[8];
        #pragma unroll
        for (int k = 0; k < 4; ++k) { wj[k] = wy0 * wzt[k]; wj[4 + k] = fy * wzt[k]; }

        // 8 table indices for this lane's x-corner
        unsigned bx = cx + xb;
        unsigned idx[8];
        if (L.mode == 0) {
            unsigned base0 = bx + cy * L.s1 + cz * L.s2 + ct * L.s3;
            idx[0] = base0;
            idx[1] = base0 + L.s2;
            idx[2] = base0 + L.s3;
            idx[3] = base0 + L.s2 + L.s3;
            #pragma unroll
            for (int k = 0; k < 4; ++k) idx[4 + k] = idx[k] + L.s1;
        } else if (L.mode == 1) {
            unsigned hy = cy * HPRIME1, hz = cz * HPRIME2, ht = ct * HPRIME3;
            unsigned msk = L.mask;
            unsigned rzt[4] = { hz ^ ht, (hz + HPRIME2) ^ ht,
                                hz ^ (ht + HPRIME3), (hz + HPRIME2) ^ (ht + HPRIME3) };
            #pragma unroll
            for (int k = 0; k < 4; ++k) {
                idx[k]     = (bx ^ hy             ^ rzt[k]) & msk;
                idx[4 + k] = (bx ^ (hy + HPRIME1) ^ rzt[k]) & msk;
            }
        } else {
            // generic mod fallback (never taken with current constants)
            unsigned hy = cy * HPRIME1, hz = cz * HPRIME2, ht = ct * HPRIME3;
            unsigned sz = L.size;
            unsigned rzt[4] = { hz ^ ht, (hz + HPRIME2) ^ ht,
                                hz ^ (ht + HPRIME3), (hz + HPRIME2) ^ (ht + HPRIME3) };
            #pragma unroll
            for (int k = 0; k < 4; ++k) {
                idx[k]     = (bx ^ hy             ^ rzt[k]) % sz;
                idx[4 + k] = (bx ^ (hy + HPRIME1) ^ rzt[k]) % sz;
            }
        }

        const float2* t2 = reinterpret_cast<const float2*>(tab) + (L.offset >> 1);
        float a0 = 0.f, a1 = 0.f;
        #pragma unroll
        for (int k = 0; k < 8; ++k) {
            float2 f = __ldg(t2 + idx[k]);    // pair lanes hit the same 128B line
            a0 += wj[k] * f.x;
            a1 += wj[k] * f.y;
        }
        a0 *= wxs;
        a1 *= wxs;
        a0 += __shfl_xor_sync(amask, a0, 1);
        a1 += __shfl_xor_sync(amask, a1, 1);
        // both lanes now hold this level's (a0,a1)

        // buffer this lane's share of the 4-level group
        int j = s & 3;
        bool mine = xb ? (j >= 2) : (j < 2);      // even: levels 4g,4g+1; odd: 4g+2,4g+3
        int  lo   = xb ? (j - 2) : j;             // 0 or 1 within this lane's float4
        if (mine) {
            if (lo == 0) { r0 = a0; r1 = a1; }
            else         { r2 = a0; r3 = a1; }
        }
        if (j == 3) {
            // both lanes store into the same 128B row -> 1 coalesced wavefront
            orow[((s >> 2) << 1) + xb] = make_float4(r0, r1, r2, r3);
        }
    }
}

// ---------------------------------------------------------------------------
// Host-side config: mirrors reference build_config() op-for-op in float64.
// ---------------------------------------------------------------------------
static KConfig build_cfg_host()
{
    const double minr[4] = {16.0, 16.0, 16.0, 16.0};
    const double maxr[4] = {256.0, 256.0, 256.0, 128.0};
    const long long MAXP = 524288; // 2^19

    double b[4];
    for (int d = 0; d < 4; ++d)
        b[d] = exp((log(maxr[d]) - log(minr[d])) / 15.0);

    KConfig cfg;
    long long total = 0;
    for (int s = 0; s < 16; ++s) {
        long long res[4];
        for (int d = 0; d < 4; ++d)
            res[d] = (long long)ceil(minr[d] * pow(b[d], (double)s));
        long long raw = (res[0] + 1) * (res[1] + 1) * (res[2] + 1) * (res[3] + 1);
        long long p = (raw % 8 == 0) ? raw : ((raw + 7) / 8) * 8;
        if (p > MAXP) p = MAXP;
        int dense = (raw <= p) ? 1 : 0;

        Level& L = cfg.lv[s];
        L.rf0 = (float)res[0]; L.rf1 = (float)res[1];
        L.rf2 = (float)res[2]; L.rf3 = (float)res[3];
        L.s1 = (unsigned)(res[0] + 1);
        L.s2 = (unsigned)((res[0] + 1) * (res[1] + 1));
        L.s3 = (unsigned)((res[0] + 1) * (res[1] + 1) * (res[2] + 1));
        L.size = (unsigned)p;
        L.mask = (unsigned)(p - 1);
        L.offset = (int)total;
        if (dense)                      L.mode = 0;
        else if ((p & (p - 1)) == 0)    L.mode = 1;
        else                            L.mode = 2;
        total += p * 2;  // F = 2
    }
    return cfg;
}

extern "C" void kernel_launch(void* const* d_in, const int* in_sizes, int n_in,
                              void* d_out, int out_size)
{
    static KConfig cfg = build_cfg_host();

    const float4* xyzt = (const float4*)d_in[0];
    const float*  tab  = (const float*)d_in[1];
    float*        out  = (float*)d_out;

    int n = in_sizes[0] / 4;
    long long threads = 2LL * n;
    int blocks = (int)((threads + 255) / 256);
    hashenc_kernel<<<blocks, 256>>>(xyzt, tab, out, cfg, n);
}